// round 10
// baseline (speedup 1.0000x reference)
#include <cuda_runtime.h>
#include <math.h>
#include <stdint.h>

#define NN 32768
#define KK 512
#define DD 64
#define SK_ITERS 100
#define FB 148
#define RPB ((NN + FB - 1) / FB)   // 222

__device__ __align__(16) double g_Ed[(size_t)NN * KK];  // E (f64), 128 MiB
__device__ __align__(16) float  g_D[(size_t)NN * KK];   // d, then dc (f32)
__device__ float    g_rx[NN], g_rc[KK];
__device__ double   g_vd[KK];
__device__ double   g_lnv[KK];
__device__ double   g_pd[FB * KK];
__device__ unsigned g_dmax_u, g_dmin_u;
__device__ float    g_mid, g_amp;
__device__ double   g_loss;

__global__ void k_init() {
    int t = threadIdx.x;
    if (t < KK) g_vd[t] = 1.0;
    if (t == 0) { g_dmax_u = 0u; g_dmin_u = 0x7f7fffffu; g_loss = 0.0; }
}

// XLA:GPU-style warp row-reduce: lane t takes {t, t+32} (squares rounded
// separately, then added), then shuffle butterfly tree strides 16..1.
__global__ void k_rx(const float* __restrict__ x) {
    int warp = (blockIdx.x * blockDim.x + threadIdx.x) >> 5;
    int lane = threadIdx.x & 31;
    if (warp >= NN) return;
    const float* p = x + (size_t)warp * DD;
    float s = __fadd_rn(__fmul_rn(p[lane], p[lane]),
                        __fmul_rn(p[lane + 32], p[lane + 32]));
    #pragma unroll
    for (int o = 16; o; o >>= 1) s = __fadd_rn(s, __shfl_xor_sync(~0u, s, o));
    if (lane == 0) g_rx[warp] = s;
}
__global__ void k_rc(const float* __restrict__ cb) {
    int warp = (blockIdx.x * blockDim.x + threadIdx.x) >> 5;
    int lane = threadIdx.x & 31;
    if (warp >= KK) return;
    const float* p = cb + (size_t)warp * DD;
    float s = __fadd_rn(__fmul_rn(p[lane], p[lane]),
                        __fmul_rn(p[lane + 32], p[lane + 32]));
    #pragma unroll
    for (int o = 16; o; o >>= 1) s = __fadd_rn(s, __shfl_xor_sync(~0u, s, o));
    if (lane == 0) g_rc[warp] = s;
}

// d = fl(fl(rx+rc) - fl(2*mm)); mm = strict ascending-k single-FMA f32 chain
__global__ __launch_bounds__(256) void k_gemm(const float* __restrict__ x,
                                              const float* __restrict__ cb) {
    __shared__ float xs[128][DD];
    __shared__ float cs[32][DD + 1];
    __shared__ float red[16];
    int b = blockIdx.x, row0 = b * 128, t = threadIdx.x;
    int jj = t & 31, rg = t >> 5;

    for (int i = t; i < 128 * DD; i += 256)
        xs[i / DD][i % DD] = x[(size_t)row0 * DD + i];

    float dmx = 0.0f, dmn = 3.4e38f;
    for (int ct = 0; ct < 16; ct++) {
        __syncthreads();
        for (int i = t; i < 32 * DD; i += 256)
            cs[i / DD][i % DD] = cb[(size_t)(ct * 32) * DD + i];
        __syncthreads();
        float cj[DD];
        #pragma unroll
        for (int k = 0; k < DD; k++) cj[k] = cs[jj][k];
        int jglob = ct * 32 + jj;
        float rcj = g_rc[jglob];

        for (int ii = 0; ii < 16; ii += 4) {
            int i0 = rg * 16 + ii;
            float a0 = 0.f, a1 = 0.f, a2 = 0.f, a3 = 0.f;
            #pragma unroll
            for (int k4 = 0; k4 < DD; k4 += 4) {
                float4 x0 = *(const float4*)&xs[i0 + 0][k4];
                float4 x1 = *(const float4*)&xs[i0 + 1][k4];
                float4 x2 = *(const float4*)&xs[i0 + 2][k4];
                float4 x3 = *(const float4*)&xs[i0 + 3][k4];
                a0 = __fmaf_rn(x0.x, cj[k4+0], a0); a0 = __fmaf_rn(x0.y, cj[k4+1], a0);
                a0 = __fmaf_rn(x0.z, cj[k4+2], a0); a0 = __fmaf_rn(x0.w, cj[k4+3], a0);
                a1 = __fmaf_rn(x1.x, cj[k4+0], a1); a1 = __fmaf_rn(x1.y, cj[k4+1], a1);
                a1 = __fmaf_rn(x1.z, cj[k4+2], a1); a1 = __fmaf_rn(x1.w, cj[k4+3], a1);
                a2 = __fmaf_rn(x2.x, cj[k4+0], a2); a2 = __fmaf_rn(x2.y, cj[k4+1], a2);
                a2 = __fmaf_rn(x2.z, cj[k4+2], a2); a2 = __fmaf_rn(x2.w, cj[k4+3], a2);
                a3 = __fmaf_rn(x3.x, cj[k4+0], a3); a3 = __fmaf_rn(x3.y, cj[k4+1], a3);
                a3 = __fmaf_rn(x3.z, cj[k4+2], a3); a3 = __fmaf_rn(x3.w, cj[k4+3], a3);
            }
            float mm[4] = {a0, a1, a2, a3};
            #pragma unroll
            for (int r = 0; r < 4; r++) {
                int i = i0 + r;
                float S = __fadd_rn(g_rx[row0 + i], rcj);
                float d = __fsub_rn(S, __fmul_rn(2.0f, mm[r]));
                dmx = fmaxf(dmx, d); dmn = fminf(dmn, d);
                g_D[(size_t)(row0 + i) * KK + jglob] = d;
            }
        }
    }
    #pragma unroll
    for (int o = 16; o; o >>= 1) {
        dmx = fmaxf(dmx, __shfl_xor_sync(~0u, dmx, o));
        dmn = fminf(dmn, __shfl_xor_sync(~0u, dmn, o));
    }
    int w = t >> 5;
    if ((t & 31) == 0) { red[w] = dmx; red[w + 8] = dmn; }
    __syncthreads();
    if (t == 0) {
        float m = red[0], n = red[8];
        for (int i = 1; i < 8; i++) { m = fmaxf(m, red[i]); n = fminf(n, red[i + 8]); }
        atomicMax(&g_dmax_u, __float_as_uint(m));
        atomicMin(&g_dmin_u, __float_as_uint(n));
    }
}

__global__ void k_scale() {
    float dmax = __uint_as_float(g_dmax_u), dmin = __uint_as_float(g_dmin_u);
    float mid = __fmul_rn(__fadd_rn(dmax, dmin), 0.5f);
    g_mid = mid;
    g_amp = __fadd_rn(__fsub_rn(dmax, mid), 1e-5f);
}

// dc = fl((d-mid)/amp) bitwise -> g_D;  E = exp(sh - dc/0.003) f64 -> g_Ed
__global__ __launch_bounds__(256) void k_rowE() {
    int warp = (blockIdx.x * blockDim.x + threadIdx.x) >> 5;
    int lane = threadIdx.x & 31;
    if (warp >= NN) return;
    float mid = g_mid, amp = g_amp;
    float4*  Dr = (float4*)&g_D[(size_t)warp * KK];
    double2* Er = (double2*)&g_Ed[(size_t)warp * KK];

    float4 dcv[4];
    float rmin = 3.4e38f;
    #pragma unroll
    for (int k = 0; k < 4; k++) {
        float4 d = Dr[lane + 32 * k];
        d.x = __fdiv_rn(__fsub_rn(d.x, mid), amp);
        d.y = __fdiv_rn(__fsub_rn(d.y, mid), amp);
        d.z = __fdiv_rn(__fsub_rn(d.z, mid), amp);
        d.w = __fdiv_rn(__fsub_rn(d.w, mid), amp);
        rmin = fminf(rmin, fminf(fminf(d.x, d.y), fminf(d.z, d.w)));
        dcv[k] = d;
    }
    #pragma unroll
    for (int o = 16; o; o >>= 1) rmin = fminf(rmin, __shfl_xor_sync(~0u, rmin, o));

    double sh = (double)rmin / 0.003;   // row shift (argmax & v invariant)
    #pragma unroll
    for (int k = 0; k < 4; k++) {
        float4 d = dcv[k];
        Dr[lane + 32 * k] = d;
        double2 e0, e1;
        e0.x = exp(sh - (double)d.x / 0.003);
        e0.y = exp(sh - (double)d.y / 0.003);
        e1.x = exp(sh - (double)d.z / 0.003);
        e1.y = exp(sh - (double)d.w / 0.003);
        Er[2 * (lane + 32 * k) + 0] = e0;
        Er[2 * (lane + 32 * k) + 1] = e1;
    }
}

// one Sinkhorn iteration, fully f64
__global__ __launch_bounds__(256) void k_sink() {
    __shared__ double sh[8][KK];
    int b = blockIdx.x, t = threadIdx.x, w = t >> 5, lane = t & 31;
    int row0 = b * RPB, row1 = min(row0 + RPB, NN);

    double vr[16];
    #pragma unroll
    for (int k = 0; k < 8; k++) {
        int c2 = lane + 32 * k;
        vr[2 * k + 0] = g_vd[2 * c2 + 0];
        vr[2 * k + 1] = g_vd[2 * c2 + 1];
    }
    double acc[16];
    #pragma unroll
    for (int m = 0; m < 16; m++) acc[m] = 0.0;

    for (int r = row0 + w; r < row1; r += 8) {
        const double2* Er = (const double2*)&g_Ed[(size_t)r * KK];
        double2 e[8];
        #pragma unroll
        for (int k = 0; k < 8; k++) e[k] = Er[lane + 32 * k];
        double s0 = 0.0, s1 = 0.0;
        #pragma unroll
        for (int k = 0; k < 8; k++) {
            s0 = fma(e[k].x, vr[2 * k + 0], s0);
            s1 = fma(e[k].y, vr[2 * k + 1], s1);
        }
        double dot = s0 + s1;
        #pragma unroll
        for (int o = 16; o; o >>= 1) dot += __shfl_xor_sync(~0u, dot, o);
        double u = 1.0 / (32768.0 * dot);
        #pragma unroll
        for (int k = 0; k < 8; k++) {
            acc[2 * k + 0] = fma(e[k].x, u, acc[2 * k + 0]);
            acc[2 * k + 1] = fma(e[k].y, u, acc[2 * k + 1]);
        }
    }
    #pragma unroll
    for (int k = 0; k < 8; k++) {
        int c2 = lane + 32 * k;
        sh[w][2 * c2 + 0] = acc[2 * k + 0];
        sh[w][2 * c2 + 1] = acc[2 * k + 1];
    }
    __syncthreads();
    for (int j = t; j < KK; j += 256) {
        double a = 0.0;
        #pragma unroll
        for (int wi = 0; wi < 8; wi++) a += sh[wi][j];
        g_pd[b * KK + j] = a;
    }
}

__global__ void k_colfin() {
    int j = threadIdx.x;  // 512
    double s = 0.0;
    for (int b = 0; b < FB; b++) s += g_pd[b * KK + j];
    if (s < 1e-300) s = 1e-300;
    double v = 1.0 / (512.0 * s);
    g_vd[j] = v;
    g_lnv[j] = log(v);
}

// final: f64 scores s_j = ln v_j - dc_ij/0.003
__global__ void k_out(const float* __restrict__ x, const float* __restrict__ cb,
                      float* __restrict__ oxq, float* __restrict__ oidx) {
    int warp = (blockIdx.x * blockDim.x + threadIdx.x) >> 5;
    int lane = threadIdx.x & 31;
    if (warp >= NN) return;
    int r = warp;

    const float4* Dr = (const float4*)&g_D[(size_t)r * KK];
    double best = -1e300;
    int bidx = 0;
    #pragma unroll
    for (int k = 0; k < 4; k++) {
        float4 d = Dr[lane + 32 * k];
        int c0 = 4 * lane + 128 * k;
        float dv[4] = {d.x, d.y, d.z, d.w};
        #pragma unroll
        for (int c = 0; c < 4; c++) {
            double s = g_lnv[c0 + c] - (double)dv[c] / 0.003;
            if (s > best) { best = s; bidx = c0 + c; }
        }
    }
    #pragma unroll
    for (int o = 16; o; o >>= 1) {
        double ov = __shfl_xor_sync(~0u, best, o);
        int oi = __shfl_xor_sync(~0u, bidx, o);
        if (ov > best || (ov == best && oi < bidx)) { best = ov; bidx = oi; }
    }

    const float* c = cb + (size_t)bidx * DD;
    const float* xr = x + (size_t)r * DD;
    float a0 = c[lane], a1 = c[lane + 32];
    float x0 = xr[lane], x1 = xr[lane + 32];
    if (oxq) {
        oxq[(size_t)r * DD + lane]      = __fadd_rn(x0, __fsub_rn(a0, x0));
        oxq[(size_t)r * DD + lane + 32] = __fadd_rn(x1, __fsub_rn(a1, x1));
    }
    float d0 = __fsub_rn(a0, x0), d1 = __fsub_rn(a1, x1);
    double ls = (double)__fmul_rn(d0, d0) + (double)__fmul_rn(d1, d1);
    #pragma unroll
    for (int o = 16; o; o >>= 1) ls += __shfl_xor_sync(~0u, ls, o);
    if (lane == 0) {
        if (oidx) oidx[r] = (float)bidx;
        atomicAdd(&g_loss, ls);
    }
}

__global__ void k_loss(float* __restrict__ ol) {
    if (ol) {
        float c = (float)(g_loss / (double)((size_t)NN * DD));
        ol[0] = __fadd_rn(c, __fmul_rn(0.25f, c));
    }
}

extern "C" void kernel_launch(void* const* d_in, const int* in_sizes, int n_in,
                              void* d_out, int out_size) {
    const float* x = (const float*)d_in[0];
    const float* cb = (const float*)d_in[1];
    if (n_in >= 2 && in_sizes[0] == KK * DD && in_sizes[1] == NN * DD) {
        const float* tmp = x; x = cb; cb = tmp;
    }
    float* out = (float*)d_out;
    float* oxq = (out_size >= NN * DD) ? out : nullptr;
    float* ols = (out_size >= NN * DD + 1) ? out + (size_t)NN * DD : nullptr;
    float* oidx = (out_size >= NN * DD + 1 + NN) ? out + (size_t)NN * DD + 1 : nullptr;

    k_init<<<1, 512>>>();
    k_rx<<<NN / 8, 256>>>(x);
    k_rc<<<KK / 8, 256>>>(cb);
    k_gemm<<<NN / 128, 256>>>(x, cb);
    k_scale<<<1, 1>>>();
    k_rowE<<<NN / 8, 256>>>();
    for (int it = 0; it < SK_ITERS; it++) {
        k_sink<<<FB, 256>>>();
        k_colfin<<<1, KK>>>();
    }
    k_out<<<NN / 8, 256>>>(x, cb, oxq, oidx);
    k_loss<<<1, 1>>>(ols);
}

// round 11
// speedup vs baseline: 2.1493x; 2.1493x over previous
#include <cuda_runtime.h>
#include <math.h>
#include <stdint.h>

#define NN 32768
#define KK 512
#define DD 64
#define SK_ITERS 100
#define FB 148
#define RPB ((NN + FB - 1) / FB)   // 222

__device__ __align__(16) float  g_E[(size_t)NN * KK];   // E (f32), 64 MiB
__device__ __align__(16) float  g_D[(size_t)NN * KK];   // d, then dc (f32)
__device__ float    g_rx[NN], g_rc[KK];
__device__ __align__(16) float g_vf[KK];
__device__ double   g_lnv[KK];
__device__ double   g_pd[FB * KK];
__device__ unsigned g_dmax_u, g_dmin_u;
__device__ float    g_mid, g_amp;
__device__ double   g_loss;

__global__ void k_init() {
    int t = threadIdx.x;
    if (t < KK) g_vf[t] = 1.0f;
    if (t == 0) { g_dmax_u = 0u; g_dmin_u = 0x7f7fffffu; g_loss = 0.0; }
}

// XLA:GPU warp row-reduce (bitwise-frozen: this is what made rel_err = 0)
__global__ void k_rx(const float* __restrict__ x) {
    int warp = (blockIdx.x * blockDim.x + threadIdx.x) >> 5;
    int lane = threadIdx.x & 31;
    if (warp >= NN) return;
    const float* p = x + (size_t)warp * DD;
    float s = __fadd_rn(__fmul_rn(p[lane], p[lane]),
                        __fmul_rn(p[lane + 32], p[lane + 32]));
    #pragma unroll
    for (int o = 16; o; o >>= 1) s = __fadd_rn(s, __shfl_xor_sync(~0u, s, o));
    if (lane == 0) g_rx[warp] = s;
}
__global__ void k_rc(const float* __restrict__ cb) {
    int warp = (blockIdx.x * blockDim.x + threadIdx.x) >> 5;
    int lane = threadIdx.x & 31;
    if (warp >= KK) return;
    const float* p = cb + (size_t)warp * DD;
    float s = __fadd_rn(__fmul_rn(p[lane], p[lane]),
                        __fmul_rn(p[lane + 32], p[lane + 32]));
    #pragma unroll
    for (int o = 16; o; o >>= 1) s = __fadd_rn(s, __shfl_xor_sync(~0u, s, o));
    if (lane == 0) g_rc[warp] = s;
}

// d = fl(fl(rx+rc) - fl(2*mm)); mm = strict ascending-k single-FMA f32 chain (frozen)
__global__ __launch_bounds__(256) void k_gemm(const float* __restrict__ x,
                                              const float* __restrict__ cb) {
    __shared__ float xs[128][DD];
    __shared__ float cs[32][DD + 1];
    __shared__ float red[16];
    int b = blockIdx.x, row0 = b * 128, t = threadIdx.x;
    int jj = t & 31, rg = t >> 5;

    for (int i = t; i < 128 * DD; i += 256)
        xs[i / DD][i % DD] = x[(size_t)row0 * DD + i];

    float dmx = 0.0f, dmn = 3.4e38f;
    for (int ct = 0; ct < 16; ct++) {
        __syncthreads();
        for (int i = t; i < 32 * DD; i += 256)
            cs[i / DD][i % DD] = cb[(size_t)(ct * 32) * DD + i];
        __syncthreads();
        float cj[DD];
        #pragma unroll
        for (int k = 0; k < DD; k++) cj[k] = cs[jj][k];
        int jglob = ct * 32 + jj;
        float rcj = g_rc[jglob];

        for (int ii = 0; ii < 16; ii += 4) {
            int i0 = rg * 16 + ii;
            float a0 = 0.f, a1 = 0.f, a2 = 0.f, a3 = 0.f;
            #pragma unroll
            for (int k4 = 0; k4 < DD; k4 += 4) {
                float4 x0 = *(const float4*)&xs[i0 + 0][k4];
                float4 x1 = *(const float4*)&xs[i0 + 1][k4];
                float4 x2 = *(const float4*)&xs[i0 + 2][k4];
                float4 x3 = *(const float4*)&xs[i0 + 3][k4];
                a0 = __fmaf_rn(x0.x, cj[k4+0], a0); a0 = __fmaf_rn(x0.y, cj[k4+1], a0);
                a0 = __fmaf_rn(x0.z, cj[k4+2], a0); a0 = __fmaf_rn(x0.w, cj[k4+3], a0);
                a1 = __fmaf_rn(x1.x, cj[k4+0], a1); a1 = __fmaf_rn(x1.y, cj[k4+1], a1);
                a1 = __fmaf_rn(x1.z, cj[k4+2], a1); a1 = __fmaf_rn(x1.w, cj[k4+3], a1);
                a2 = __fmaf_rn(x2.x, cj[k4+0], a2); a2 = __fmaf_rn(x2.y, cj[k4+1], a2);
                a2 = __fmaf_rn(x2.z, cj[k4+2], a2); a2 = __fmaf_rn(x2.w, cj[k4+3], a2);
                a3 = __fmaf_rn(x3.x, cj[k4+0], a3); a3 = __fmaf_rn(x3.y, cj[k4+1], a3);
                a3 = __fmaf_rn(x3.z, cj[k4+2], a3); a3 = __fmaf_rn(x3.w, cj[k4+3], a3);
            }
            float mm[4] = {a0, a1, a2, a3};
            #pragma unroll
            for (int r = 0; r < 4; r++) {
                int i = i0 + r;
                float S = __fadd_rn(g_rx[row0 + i], rcj);
                float d = __fsub_rn(S, __fmul_rn(2.0f, mm[r]));
                dmx = fmaxf(dmx, d); dmn = fminf(dmn, d);
                g_D[(size_t)(row0 + i) * KK + jglob] = d;
            }
        }
    }
    #pragma unroll
    for (int o = 16; o; o >>= 1) {
        dmx = fmaxf(dmx, __shfl_xor_sync(~0u, dmx, o));
        dmn = fminf(dmn, __shfl_xor_sync(~0u, dmn, o));
    }
    int w = t >> 5;
    if ((t & 31) == 0) { red[w] = dmx; red[w + 8] = dmn; }
    __syncthreads();
    if (t == 0) {
        float m = red[0], n = red[8];
        for (int i = 1; i < 8; i++) { m = fmaxf(m, red[i]); n = fminf(n, red[i + 8]); }
        atomicMax(&g_dmax_u, __float_as_uint(m));
        atomicMin(&g_dmin_u, __float_as_uint(n));
    }
}

__global__ void k_scale() {
    float dmax = __uint_as_float(g_dmax_u), dmin = __uint_as_float(g_dmin_u);
    float mid = __fmul_rn(__fadd_rn(dmax, dmin), 0.5f);
    g_mid = mid;
    g_amp = __fadd_rn(__fsub_rn(dmax, mid), 1e-5f);
}

// dc = fl((d-mid)/amp) bitwise -> g_D;  E = (float)exp(sh - dc/0.003) -> g_E
__global__ __launch_bounds__(256) void k_rowE() {
    int warp = (blockIdx.x * blockDim.x + threadIdx.x) >> 5;
    int lane = threadIdx.x & 31;
    if (warp >= NN) return;
    float mid = g_mid, amp = g_amp;
    float4* Dr = (float4*)&g_D[(size_t)warp * KK];
    float4* Er = (float4*)&g_E[(size_t)warp * KK];

    float4 dcv[4];
    float rmin = 3.4e38f;
    #pragma unroll
    for (int k = 0; k < 4; k++) {
        float4 d = Dr[lane + 32 * k];
        d.x = __fdiv_rn(__fsub_rn(d.x, mid), amp);
        d.y = __fdiv_rn(__fsub_rn(d.y, mid), amp);
        d.z = __fdiv_rn(__fsub_rn(d.z, mid), amp);
        d.w = __fdiv_rn(__fsub_rn(d.w, mid), amp);
        rmin = fminf(rmin, fminf(fminf(d.x, d.y), fminf(d.z, d.w)));
        dcv[k] = d;
    }
    #pragma unroll
    for (int o = 16; o; o >>= 1) rmin = fminf(rmin, __shfl_xor_sync(~0u, rmin, o));

    double sh = (double)rmin / 0.003;   // row shift (argmax & v invariant)
    #pragma unroll
    for (int k = 0; k < 4; k++) {
        float4 d = dcv[k], e;
        Dr[lane + 32 * k] = d;
        e.x = (float)exp(sh - (double)d.x / 0.003);
        e.y = (float)exp(sh - (double)d.y / 0.003);
        e.z = (float)exp(sh - (double)d.z / 0.003);
        e.w = (float)exp(sh - (double)d.w / 0.003);
        Er[lane + 32 * k] = e;
    }
}

#define KAH(m, p) do {                                   \
    float _y = __fsub_rn((p), cc[m]);                    \
    float _t = __fadd_rn(cs[m], _y);                     \
    cc[m] = __fsub_rn(__fsub_rn(_t, cs[m]), _y);         \
    cs[m] = _t;                                          \
} while (0)

// one Sinkhorn iteration: f32 row pass (u precision argmax-irrelevant),
// Kahan f32 column partials + f64 block combine (R7-validated trajectory)
__global__ __launch_bounds__(256) void k_sink() {
    __shared__ float shS[8][KK];
    __shared__ float shC[8][KK];
    int b = blockIdx.x, t = threadIdx.x, w = t >> 5, lane = t & 31;
    int row0 = b * RPB, row1 = min(row0 + RPB, NN);

    float4 vr[4];
    #pragma unroll
    for (int k = 0; k < 4; k++) vr[k] = *(const float4*)&g_vf[4 * lane + 128 * k];
    float cs[16], cc[16];
    #pragma unroll
    for (int m = 0; m < 16; m++) { cs[m] = 0.f; cc[m] = 0.f; }

    for (int r = row0 + w; r < row1; r += 8) {
        const float4* Er = (const float4*)&g_E[(size_t)r * KK];
        float4 e[4];
        #pragma unroll
        for (int k = 0; k < 4; k++) e[k] = Er[lane + 32 * k];
        float d0 = 0.f, d1 = 0.f, d2 = 0.f, d3 = 0.f;
        #pragma unroll
        for (int k = 0; k < 4; k++) {
            d0 = fmaf(e[k].x, vr[k].x, d0);
            d1 = fmaf(e[k].y, vr[k].y, d1);
            d2 = fmaf(e[k].z, vr[k].z, d2);
            d3 = fmaf(e[k].w, vr[k].w, d3);
        }
        float dot = (d0 + d1) + (d2 + d3);
        #pragma unroll
        for (int o = 16; o; o >>= 1) dot += __shfl_xor_sync(~0u, dot, o);
        float u = __fdiv_rn(1.0f, 32768.0f * dot);
        #pragma unroll
        for (int k = 0; k < 4; k++) {
            float p;
            p = __fmul_rn(e[k].x, u); KAH(4*k+0, p);
            p = __fmul_rn(e[k].y, u); KAH(4*k+1, p);
            p = __fmul_rn(e[k].z, u); KAH(4*k+2, p);
            p = __fmul_rn(e[k].w, u); KAH(4*k+3, p);
        }
    }
    #pragma unroll
    for (int m = 0; m < 16; m++) {
        int j = 4 * lane + 128 * (m >> 2) + (m & 3);
        shS[w][j] = cs[m];
        shC[w][j] = cc[m];
    }
    __syncthreads();
    for (int j = t; j < KK; j += 256) {
        double a = 0.0;
        #pragma unroll
        for (int wi = 0; wi < 8; wi++)
            a += (double)shS[wi][j] - (double)shC[wi][j];
        g_pd[b * KK + j] = a;
    }
}

__global__ void k_colfin() {
    int j = threadIdx.x;  // 512
    double s = 0.0;
    for (int b = 0; b < FB; b++) s += g_pd[b * KK + j];
    if (s < 1e-300) s = 1e-300;
    double v = 1.0 / (512.0 * s);
    g_vf[j] = (float)v;
    g_lnv[j] = log(v);
}

// final: f64 scores s_j = ln v_j - dc_ij/0.003 on frozen dc
__global__ void k_out(const float* __restrict__ x, const float* __restrict__ cb,
                      float* __restrict__ oxq, float* __restrict__ oidx) {
    int warp = (blockIdx.x * blockDim.x + threadIdx.x) >> 5;
    int lane = threadIdx.x & 31;
    if (warp >= NN) return;
    int r = warp;

    const float4* Dr = (const float4*)&g_D[(size_t)r * KK];
    double best = -1e300;
    int bidx = 0;
    #pragma unroll
    for (int k = 0; k < 4; k++) {
        float4 d = Dr[lane + 32 * k];
        int c0 = 4 * lane + 128 * k;
        float dv[4] = {d.x, d.y, d.z, d.w};
        #pragma unroll
        for (int c = 0; c < 4; c++) {
            double s = g_lnv[c0 + c] - (double)dv[c] / 0.003;
            if (s > best) { best = s; bidx = c0 + c; }
        }
    }
    #pragma unroll
    for (int o = 16; o; o >>= 1) {
        double ov = __shfl_xor_sync(~0u, best, o);
        int oi = __shfl_xor_sync(~0u, bidx, o);
        if (ov > best || (ov == best && oi < bidx)) { best = ov; bidx = oi; }
    }

    const float* c = cb + (size_t)bidx * DD;
    const float* xr = x + (size_t)r * DD;
    float a0 = c[lane], a1 = c[lane + 32];
    float x0 = xr[lane], x1 = xr[lane + 32];
    if (oxq) {
        oxq[(size_t)r * DD + lane]      = __fadd_rn(x0, __fsub_rn(a0, x0));
        oxq[(size_t)r * DD + lane + 32] = __fadd_rn(x1, __fsub_rn(a1, x1));
    }
    float d0 = __fsub_rn(a0, x0), d1 = __fsub_rn(a1, x1);
    double ls = (double)__fmul_rn(d0, d0) + (double)__fmul_rn(d1, d1);
    #pragma unroll
    for (int o = 16; o; o >>= 1) ls += __shfl_xor_sync(~0u, ls, o);
    if (lane == 0) {
        if (oidx) oidx[r] = (float)bidx;
        atomicAdd(&g_loss, ls);
    }
}

__global__ void k_loss(float* __restrict__ ol) {
    if (ol) {
        float c = (float)(g_loss / (double)((size_t)NN * DD));
        ol[0] = __fadd_rn(c, __fmul_rn(0.25f, c));
    }
}

extern "C" void kernel_launch(void* const* d_in, const int* in_sizes, int n_in,
                              void* d_out, int out_size) {
    const float* x = (const float*)d_in[0];
    const float* cb = (const float*)d_in[1];
    if (n_in >= 2 && in_sizes[0] == KK * DD && in_sizes[1] == NN * DD) {
        const float* tmp = x; x = cb; cb = tmp;
    }
    float* out = (float*)d_out;
    float* oxq = (out_size >= NN * DD) ? out : nullptr;
    float* ols = (out_size >= NN * DD + 1) ? out + (size_t)NN * DD : nullptr;
    float* oidx = (out_size >= NN * DD + 1 + NN) ? out + (size_t)NN * DD + 1 : nullptr;

    k_init<<<1, 512>>>();
    k_rx<<<NN / 8, 256>>>(x);
    k_rc<<<KK / 8, 256>>>(cb);
    k_gemm<<<NN / 128, 256>>>(x, cb);
    k_scale<<<1, 1>>>();
    k_rowE<<<NN / 8, 256>>>();
    for (int it = 0; it < SK_ITERS; it++) {
        k_sink<<<FB, 256>>>();
        k_colfin<<<1, KK>>>();
    }
    k_out<<<NN / 8, 256>>>(x, cb, oxq, oidx);
    k_loss<<<1, 1>>>(ols);
}

// round 12
// speedup vs baseline: 5.5567x; 2.5853x over previous
#include <cuda_runtime.h>
#include <math.h>
#include <stdint.h>

#define NN 32768
#define KK 512
#define DD 64
#define SK_ITERS 100
#define NB 296
#define RPB ((NN + NB - 1) / NB)   // 111

__device__ __align__(16) float  g_E[(size_t)NN * KK];   // E (f32), 64 MiB
__device__ __align__(16) float  g_D[(size_t)NN * KK];   // d, then dc (f32)
__device__ float    g_rx[NN], g_rc[KK];
__device__ double   g_sum[3][KK];
__device__ double   g_lnv[KK];
__device__ unsigned g_dmax_u, g_dmin_u;
__device__ float    g_mid, g_amp;
__device__ double   g_loss;

__global__ void k_init() {
    int t = threadIdx.x;
    if (t < KK) { g_sum[0][t] = 0.0; g_sum[1][t] = 0.0; g_sum[2][t] = 0.0; }
    if (t == 0) { g_dmax_u = 0u; g_dmin_u = 0x7f7fffffu; g_loss = 0.0; }
}

// XLA:GPU warp row-reduce (bitwise-frozen)
__global__ void k_rx(const float* __restrict__ x) {
    int warp = (blockIdx.x * blockDim.x + threadIdx.x) >> 5;
    int lane = threadIdx.x & 31;
    if (warp >= NN) return;
    const float* p = x + (size_t)warp * DD;
    float s = __fadd_rn(__fmul_rn(p[lane], p[lane]),
                        __fmul_rn(p[lane + 32], p[lane + 32]));
    #pragma unroll
    for (int o = 16; o; o >>= 1) s = __fadd_rn(s, __shfl_xor_sync(~0u, s, o));
    if (lane == 0) g_rx[warp] = s;
}
__global__ void k_rc(const float* __restrict__ cb) {
    int warp = (blockIdx.x * blockDim.x + threadIdx.x) >> 5;
    int lane = threadIdx.x & 31;
    if (warp >= KK) return;
    const float* p = cb + (size_t)warp * DD;
    float s = __fadd_rn(__fmul_rn(p[lane], p[lane]),
                        __fmul_rn(p[lane + 32], p[lane + 32]));
    #pragma unroll
    for (int o = 16; o; o >>= 1) s = __fadd_rn(s, __shfl_xor_sync(~0u, s, o));
    if (lane == 0) g_rc[warp] = s;
}

// d = fl(fl(rx+rc) - fl(2*mm)); mm = strict ascending-k single-FMA f32 chain (frozen)
__global__ __launch_bounds__(256) void k_gemm(const float* __restrict__ x,
                                              const float* __restrict__ cb) {
    __shared__ float xs[128][DD];
    __shared__ float cs[32][DD + 1];
    __shared__ float red[16];
    int b = blockIdx.x, row0 = b * 128, t = threadIdx.x;
    int jj = t & 31, rg = t >> 5;

    for (int i = t; i < 128 * DD; i += 256)
        xs[i / DD][i % DD] = x[(size_t)row0 * DD + i];

    float dmx = 0.0f, dmn = 3.4e38f;
    for (int ct = 0; ct < 16; ct++) {
        __syncthreads();
        for (int i = t; i < 32 * DD; i += 256)
            cs[i / DD][i % DD] = cb[(size_t)(ct * 32) * DD + i];
        __syncthreads();
        float cj[DD];
        #pragma unroll
        for (int k = 0; k < DD; k++) cj[k] = cs[jj][k];
        int jglob = ct * 32 + jj;
        float rcj = g_rc[jglob];

        for (int ii = 0; ii < 16; ii += 4) {
            int i0 = rg * 16 + ii;
            float a0 = 0.f, a1 = 0.f, a2 = 0.f, a3 = 0.f;
            #pragma unroll
            for (int k4 = 0; k4 < DD; k4 += 4) {
                float4 x0 = *(const float4*)&xs[i0 + 0][k4];
                float4 x1 = *(const float4*)&xs[i0 + 1][k4];
                float4 x2 = *(const float4*)&xs[i0 + 2][k4];
                float4 x3 = *(const float4*)&xs[i0 + 3][k4];
                a0 = __fmaf_rn(x0.x, cj[k4+0], a0); a0 = __fmaf_rn(x0.y, cj[k4+1], a0);
                a0 = __fmaf_rn(x0.z, cj[k4+2], a0); a0 = __fmaf_rn(x0.w, cj[k4+3], a0);
                a1 = __fmaf_rn(x1.x, cj[k4+0], a1); a1 = __fmaf_rn(x1.y, cj[k4+1], a1);
                a1 = __fmaf_rn(x1.z, cj[k4+2], a1); a1 = __fmaf_rn(x1.w, cj[k4+3], a1);
                a2 = __fmaf_rn(x2.x, cj[k4+0], a2); a2 = __fmaf_rn(x2.y, cj[k4+1], a2);
                a2 = __fmaf_rn(x2.z, cj[k4+2], a2); a2 = __fmaf_rn(x2.w, cj[k4+3], a2);
                a3 = __fmaf_rn(x3.x, cj[k4+0], a3); a3 = __fmaf_rn(x3.y, cj[k4+1], a3);
                a3 = __fmaf_rn(x3.z, cj[k4+2], a3); a3 = __fmaf_rn(x3.w, cj[k4+3], a3);
            }
            float mm[4] = {a0, a1, a2, a3};
            #pragma unroll
            for (int r = 0; r < 4; r++) {
                int i = i0 + r;
                float S = __fadd_rn(g_rx[row0 + i], rcj);
                float d = __fsub_rn(S, __fmul_rn(2.0f, mm[r]));
                dmx = fmaxf(dmx, d); dmn = fminf(dmn, d);
                g_D[(size_t)(row0 + i) * KK + jglob] = d;
            }
        }
    }
    #pragma unroll
    for (int o = 16; o; o >>= 1) {
        dmx = fmaxf(dmx, __shfl_xor_sync(~0u, dmx, o));
        dmn = fminf(dmn, __shfl_xor_sync(~0u, dmn, o));
    }
    int w = t >> 5;
    if ((t & 31) == 0) { red[w] = dmx; red[w + 8] = dmn; }
    __syncthreads();
    if (t == 0) {
        float m = red[0], n = red[8];
        for (int i = 1; i < 8; i++) { m = fmaxf(m, red[i]); n = fminf(n, red[i + 8]); }
        atomicMax(&g_dmax_u, __float_as_uint(m));
        atomicMin(&g_dmin_u, __float_as_uint(n));
    }
}

__global__ void k_scale() {
    float dmax = __uint_as_float(g_dmax_u), dmin = __uint_as_float(g_dmin_u);
    float mid = __fmul_rn(__fadd_rn(dmax, dmin), 0.5f);
    g_mid = mid;
    g_amp = __fadd_rn(__fsub_rn(dmax, mid), 1e-5f);
}

// dc = fl((d-mid)/amp) bitwise -> g_D;  E = expf((rmin-dc)/eps) -> g_E (R7-validated)
__global__ __launch_bounds__(256) void k_rowE() {
    int warp = (blockIdx.x * blockDim.x + threadIdx.x) >> 5;
    int lane = threadIdx.x & 31;
    if (warp >= NN) return;
    float mid = g_mid, amp = g_amp;
    float4* Dr = (float4*)&g_D[(size_t)warp * KK];
    float4* Er = (float4*)&g_E[(size_t)warp * KK];

    float4 dcv[4];
    float rmin = 3.4e38f;
    #pragma unroll
    for (int k = 0; k < 4; k++) {
        float4 d = Dr[lane + 32 * k];
        d.x = __fdiv_rn(__fsub_rn(d.x, mid), amp);
        d.y = __fdiv_rn(__fsub_rn(d.y, mid), amp);
        d.z = __fdiv_rn(__fsub_rn(d.z, mid), amp);
        d.w = __fdiv_rn(__fsub_rn(d.w, mid), amp);
        rmin = fminf(rmin, fminf(fminf(d.x, d.y), fminf(d.z, d.w)));
        dcv[k] = d;
    }
    #pragma unroll
    for (int o = 16; o; o >>= 1) rmin = fminf(rmin, __shfl_xor_sync(~0u, rmin, o));

    const float INV_EPS = 333.33333333333333f;
    #pragma unroll
    for (int k = 0; k < 4; k++) {
        float4 d = dcv[k], e;
        Dr[lane + 32 * k] = d;
        e.x = expf(__fmul_rn(__fsub_rn(rmin, d.x), INV_EPS));
        e.y = expf(__fmul_rn(__fsub_rn(rmin, d.y), INV_EPS));
        e.z = expf(__fmul_rn(__fsub_rn(rmin, d.z), INV_EPS));
        e.w = expf(__fmul_rn(__fsub_rn(rmin, d.w), INV_EPS));
        Er[lane + 32 * k] = e;
    }
}

// one Sinkhorn iteration, fused v-recompute + row pass + atomic f64 colsums.
// buffers: prev=(it+2)%3 (read v), cur=it%3 (accumulate), nxt=(it+1)%3 (zero)
__global__ __launch_bounds__(256, 2) void k_sink(int it) {
    __shared__ float sv[KK];
    __shared__ float shS[8][KK];   // 16 KB
    int b = blockIdx.x, t = threadIdx.x, w = t >> 5, lane = t & 31;
    int row0 = b * RPB, row1 = min(row0 + RPB, NN);
    int prev = (it + 2) % 3, cur = it % 3, nxt = (it + 1) % 3;

    if (it == 0) {
        for (int j = t; j < KK; j += 256) sv[j] = 1.0f;
    } else {
        for (int j = t; j < KK; j += 256)
            sv[j] = (float)(1.0 / (512.0 * g_sum[prev][j]));
    }
    for (int j = t; j < KK; j += 256) g_sum[nxt][j] = 0.0;
    __syncthreads();

    float4 vr[4];
    #pragma unroll
    for (int k = 0; k < 4; k++) vr[k] = *(const float4*)&sv[4 * lane + 128 * k];
    float4 cpA[4], cpB[4];
    #pragma unroll
    for (int k = 0; k < 4; k++) {
        cpA[k] = make_float4(0.f, 0.f, 0.f, 0.f);
        cpB[k] = make_float4(0.f, 0.f, 0.f, 0.f);
    }

    int par = 0;
    for (int r = row0 + w; r < row1; r += 8, par ^= 1) {
        const float4* Er = (const float4*)&g_E[(size_t)r * KK];
        float4 e[4];
        #pragma unroll
        for (int k = 0; k < 4; k++) e[k] = Er[lane + 32 * k];
        float d0 = 0.f, d1 = 0.f, d2 = 0.f, d3 = 0.f;
        #pragma unroll
        for (int k = 0; k < 4; k++) {
            d0 = fmaf(e[k].x, vr[k].x, d0);
            d1 = fmaf(e[k].y, vr[k].y, d1);
            d2 = fmaf(e[k].z, vr[k].z, d2);
            d3 = fmaf(e[k].w, vr[k].w, d3);
        }
        float dot = (d0 + d1) + (d2 + d3);
        #pragma unroll
        for (int o = 16; o; o >>= 1) dot += __shfl_xor_sync(~0u, dot, o);
        float u = __fdiv_rn(1.0f, 32768.0f * dot);
        float4* cp = par ? cpB : cpA;
        #pragma unroll
        for (int k = 0; k < 4; k++) {
            cp[k].x = fmaf(e[k].x, u, cp[k].x);
            cp[k].y = fmaf(e[k].y, u, cp[k].y);
            cp[k].z = fmaf(e[k].z, u, cp[k].z);
            cp[k].w = fmaf(e[k].w, u, cp[k].w);
        }
    }
    #pragma unroll
    for (int k = 0; k < 4; k++) {
        float4 s;
        s.x = cpA[k].x + cpB[k].x; s.y = cpA[k].y + cpB[k].y;
        s.z = cpA[k].z + cpB[k].z; s.w = cpA[k].w + cpB[k].w;
        *(float4*)&shS[w][4 * lane + 128 * k] = s;
    }
    __syncthreads();
    for (int j = t; j < KK; j += 256) {
        double a = 0.0;
        #pragma unroll
        for (int wi = 0; wi < 8; wi++) a += (double)shS[wi][j];
        atomicAdd(&g_sum[cur][j], a);
    }
}

__global__ void k_lnv(int last) {
    int j = threadIdx.x;  // 512
    double s = g_sum[last][j];
    if (s < 1e-300) s = 1e-300;
    g_lnv[j] = log(1.0 / (512.0 * s));
}

// final: f64 scores s_j = ln v_j - dc_ij/0.003 on frozen dc
__global__ void k_out(const float* __restrict__ x, const float* __restrict__ cb,
                      float* __restrict__ oxq, float* __restrict__ oidx) {
    int warp = (blockIdx.x * blockDim.x + threadIdx.x) >> 5;
    int lane = threadIdx.x & 31;
    if (warp >= NN) return;
    int r = warp;

    const float4* Dr = (const float4*)&g_D[(size_t)r * KK];
    double best = -1e300;
    int bidx = 0;
    #pragma unroll
    for (int k = 0; k < 4; k++) {
        float4 d = Dr[lane + 32 * k];
        int c0 = 4 * lane + 128 * k;
        float dv[4] = {d.x, d.y, d.z, d.w};
        #pragma unroll
        for (int c = 0; c < 4; c++) {
            double s = g_lnv[c0 + c] - (double)dv[c] / 0.003;
            if (s > best) { best = s; bidx = c0 + c; }
        }
    }
    #pragma unroll
    for (int o = 16; o; o >>= 1) {
        double ov = __shfl_xor_sync(~0u, best, o);
        int oi = __shfl_xor_sync(~0u, bidx, o);
        if (ov > best || (ov == best && oi < bidx)) { best = ov; bidx = oi; }
    }

    const float* c = cb + (size_t)bidx * DD;
    const float* xr = x + (size_t)r * DD;
    float a0 = c[lane], a1 = c[lane + 32];
    float x0 = xr[lane], x1 = xr[lane + 32];
    if (oxq) {
        oxq[(size_t)r * DD + lane]      = __fadd_rn(x0, __fsub_rn(a0, x0));
        oxq[(size_t)r * DD + lane + 32] = __fadd_rn(x1, __fsub_rn(a1, x1));
    }
    float d0 = __fsub_rn(a0, x0), d1 = __fsub_rn(a1, x1);
    double ls = (double)__fmul_rn(d0, d0) + (double)__fmul_rn(d1, d1);
    #pragma unroll
    for (int o = 16; o; o >>= 1) ls += __shfl_xor_sync(~0u, ls, o);
    if (lane == 0) {
        if (oidx) oidx[r] = (float)bidx;
        atomicAdd(&g_loss, ls);
    }
}

__global__ void k_loss(float* __restrict__ ol) {
    if (ol) {
        float c = (float)(g_loss / (double)((size_t)NN * DD));
        ol[0] = __fadd_rn(c, __fmul_rn(0.25f, c));
    }
}

extern "C" void kernel_launch(void* const* d_in, const int* in_sizes, int n_in,
                              void* d_out, int out_size) {
    const float* x = (const float*)d_in[0];
    const float* cb = (const float*)d_in[1];
    if (n_in >= 2 && in_sizes[0] == KK * DD && in_sizes[1] == NN * DD) {
        const float* tmp = x; x = cb; cb = tmp;
    }
    float* out = (float*)d_out;
    float* oxq = (out_size >= NN * DD) ? out : nullptr;
    float* ols = (out_size >= NN * DD + 1) ? out + (size_t)NN * DD : nullptr;
    float* oidx = (out_size >= NN * DD + 1 + NN) ? out + (size_t)NN * DD + 1 : nullptr;

    k_init<<<1, 512>>>();
    k_rx<<<NN / 8, 256>>>(x);
    k_rc<<<KK / 8, 256>>>(cb);
    k_gemm<<<NN / 128, 256>>>(x, cb);
    k_scale<<<1, 1>>>();
    k_rowE<<<NN / 8, 256>>>();
    for (int it = 0; it < SK_ITERS; it++)
        k_sink<<<NB, 256>>>(it);
    k_lnv<<<1, KK>>>((SK_ITERS - 1) % 3);
    k_out<<<NN / 8, 256>>>(x, cb, oxq, oidx);
    k_loss<<<1, 1>>>(ols);
}